// round 14
// baseline (speedup 1.0000x reference)
#include <cuda_runtime.h>
#include <cuda_bf16.h>
#include <cuda_fp16.h>
#include <cuda_fp8.h>
#include <cstdint>
#include <cstddef>

#define VOCAB 91557
#define WD    512
#define HID   1024
#define NB    256
#define TT    128
#define BQ    512
#define N4H   4096
#define MX    (BQ*TT)

#define KC     128                // K chunk in fp8 elems (=128 B)
#define ROWB   144                // padded row bytes
#define ATILE  (128*ROWB)         // 18432 B per operand chunk
#define STAGEB (2*ATILE)          // A+B = 36864 B
#define NSTG   3
#define SMEMB  (NSTG*STAGEB)      // 110592 B

#define SCALE_IN   64.0f
#define INV_SC2    (1.0f/4096.0f)

// ---------------- static scratch (no allocs allowed) ----------------
__device__ unsigned char g_emb_f8[(size_t)VOCAB*WD];        // ~47 MB
__device__ unsigned char g_Wih_f8[(size_t)N4H*WD];          // 2 MB, col = 4*h+gate
__device__ unsigned char g_Whh_f8[(size_t)N4H*HID];         // 4 MB
__device__ float         g_bias_r[N4H];
__device__ __nv_bfloat16 g_X[(size_t)MX*N4H];               // 512 MB bf16
__device__ unsigned char g_Hbuf[2][(size_t)BQ*HID];         // fp8, x64 scaled
__device__ float         g_Hmax[(size_t)BQ*HID];
__device__ unsigned      g_bar4[4*32];                      // 4 group counters, 128B apart

__device__ __forceinline__ float sigf(float x){ return 1.f/(1.f+__expf(-x)); }
__device__ __forceinline__ float tanhf_(float x){ return 2.f/(1.f+__expf(-2.f*x)) - 1.f; }

__device__ __forceinline__ unsigned char to_f8(float x){
  return (unsigned char)__nv_cvt_float_to_fp8(x, __NV_SATFINITE, __NV_E4M3);
}

// fp8 e4m3 mma, m16n8k32, fp16 accumulate (2 packed regs)
__device__ __forceinline__ void mma_f8h(uint32_t* c, const uint32_t* a, const uint32_t* b){
  asm volatile(
    "mma.sync.aligned.m16n8k32.row.col.f16.e4m3.e4m3.f16 "
    "{%0,%1}, {%2,%3,%4,%5}, {%6,%7}, {%0,%1};\n"
    : "+r"(c[0]), "+r"(c[1])
    : "r"(a[0]), "r"(a[1]), "r"(a[2]), "r"(a[3]), "r"(b[0]), "r"(b[1]));
}

__device__ __forceinline__ void ldm_x4(uint32_t* r, uint32_t addr){
  asm volatile("ldmatrix.sync.aligned.m8n8.x4.shared.b16 {%0,%1,%2,%3}, [%4];"
    : "=r"(r[0]), "=r"(r[1]), "=r"(r[2]), "=r"(r[3]) : "r"(addr));
}

__device__ __forceinline__ uint32_t su32(const void* p){
  uint32_t a;
  asm("{ .reg .u64 t; cvta.to.shared.u64 t, %1; cvt.u32.u64 %0, t; }" : "=r"(a) : "l"(p));
  return a;
}
__device__ __forceinline__ void cp16(uint32_t dst, const void* src){
  asm volatile("cp.async.cg.shared.global [%0], [%1], 16;\n" :: "r"(dst), "l"(src));
}
__device__ __forceinline__ void cp_commit(){ asm volatile("cp.async.commit_group;\n"); }
__device__ __forceinline__ void cp_wait0(){ asm volatile("cp.async.wait_group 0;\n"); }
__device__ __forceinline__ void cp_wait1(){ asm volatile("cp.async.wait_group 1;\n"); }

// ---------------- prep kernels ----------------
__global__ void k_cast_emb(const float* __restrict__ emb){
  size_t n = (size_t)VOCAB*WD/4;
  size_t stride = (size_t)gridDim.x*blockDim.x;
  for (size_t i = (size_t)blockIdx.x*blockDim.x + threadIdx.x; i < n; i += stride){
    float4 v = ((const float4*)emb)[i];
    uchar4 o;
    o.x = to_f8(v.x*SCALE_IN); o.y = to_f8(v.y*SCALE_IN);
    o.z = to_f8(v.z*SCALE_IN); o.w = to_f8(v.w*SCALE_IN);
    ((uchar4*)g_emb_f8)[i] = o;
  }
}
// merged: Wih reorder + Whh reorder + bias + barrier reset
__global__ void k_prep(const float* __restrict__ Wih, const float* __restrict__ Whh,
                       const float* __restrict__ b_ih, const float* __restrict__ b_hh){
  size_t stride = (size_t)gridDim.x*blockDim.x;
  size_t i0 = (size_t)blockIdx.x*blockDim.x + threadIdx.x;
  const size_t nih = (size_t)N4H*WD;
  for (size_t i = i0; i < nih; i += stride){
    size_t nn = i / WD, k = i - nn*WD;
    size_t h = nn >> 2, g = nn & 3;
    g_Wih_f8[i] = to_f8(Wih[(g*HID + h)*WD + k]*SCALE_IN);
  }
  const size_t nhh = (size_t)N4H*HID;
  for (size_t i = i0; i < nhh; i += stride){
    size_t nn = i / HID, k = i - nn*HID;
    size_t h = nn >> 2, g = nn & 3;
    g_Whh_f8[i] = to_f8(Whh[(g*HID + h)*HID + k]*SCALE_IN);
  }
  for (size_t i = i0; i < N4H; i += stride){
    size_t h = i >> 2, g = i & 3;
    g_bias_r[i] = b_ih[g*HID + h] + b_hh[g*HID + h];
  }
  if (i0 < 4) g_bar4[i0*32] = 0u;
}

// ================= X = gather(emb) @ Wih^T + bias (fp8, f16 acc) =================
__global__ __launch_bounds__(512,1) void k_xgemm(const int* __restrict__ question,
                                                 const int* __restrict__ sentence){
  extern __shared__ __align__(16) char sb[];
  __shared__ int toks[128];

  int tid  = threadIdx.x;
  int n0   = blockIdx.x * 128;
  int m0   = blockIdx.y * 128;
  int t    = m0 / BQ;

  if (tid < 128){
    int b = (m0 % BQ) + tid;
    toks[tid] = (b < NB) ? question[b*TT + t] : sentence[(b-NB)*TT + t];
  }
  __syncthreads();

  int lane = tid & 31, warp = tid >> 5;
  int wm = warp >> 2, wn = warp & 3;          // 4x4 warp grid, 32x32 warp tiles
  uint32_t smembase = su32(sb);

  uint32_t aoff = (uint32_t)((wm*32 + (lane & 15))*ROWB + ((lane >> 4) << 4));
  uint32_t boff = (uint32_t)(ATILE + (wn*32 + (lane & 7) + (((lane >> 4) & 1) << 3))*ROWB
                             + (((lane >> 3) & 1) << 4));

  uint32_t acc[2][4][2];
  #pragma unroll
  for (int a=0;a<2;a++)
    #pragma unroll
    for (int b=0;b<4;b++){ acc[a][b][0]=0u; acc[a][b][1]=0u; }

  const int NC = WD / KC;   // 4

  auto fill = [&](int kc){
    int s = kc % NSTG;
    uint32_t base = smembase + s*STAGEB;
    int k0 = kc * KC;
    #pragma unroll
    for (int p=0; p<2; p++){
      int seg = tid + p*512;
      int row = seg >> 3, cs = seg & 7;
      uint32_t d = base + row*ROWB + cs*16;
      cp16(d,         g_emb_f8 + (size_t)toks[row]*WD + k0 + cs*16);
      cp16(d + ATILE, g_Wih_f8 + (size_t)(n0+row)*WD + k0 + cs*16);
    }
    cp_commit();
  };

  fill(0); fill(1);

  #pragma unroll 1
  for (int kc = 0; kc < NC; kc++){
    if (kc < NC-1) cp_wait1(); else cp_wait0();
    __syncthreads();
    if (kc + 2 < NC) fill(kc + 2);

    uint32_t ab = smembase + (kc % NSTG)*STAGEB + aoff;
    uint32_t bb = smembase + (kc % NSTG)*STAGEB + boff;
    #pragma unroll
    for (int kk = 0; kk < 4; kk++){     // 4 sub-k of 32 fp8 (32 B)
      uint32_t ko = kk*32;
      uint32_t afr[2][4], bfr[2][4];
      ldm_x4(afr[0], ab + ko);
      ldm_x4(afr[1], ab + 16*ROWB + ko);
      ldm_x4(bfr[0], bb + ko);
      ldm_x4(bfr[1], bb + 16*ROWB + ko);
      #pragma unroll
      for (int mi=0; mi<2; mi++){
        mma_f8h(acc[mi][0], afr[mi], &bfr[0][0]);
        mma_f8h(acc[mi][1], afr[mi], &bfr[0][2]);
        mma_f8h(acc[mi][2], afr[mi], &bfr[1][0]);
        mma_f8h(acc[mi][3], afr[mi], &bfr[1][2]);
      }
    }
  }

  // epilogue: unpack f16 acc, descale, + bias, store bf16
  #pragma unroll
  for (int mi=0; mi<2; mi++)
    #pragma unroll
    for (int nj=0; nj<4; nj++){
      int r0 = wm*32 + mi*16 + (lane>>2);
      int c0 = wn*32 + nj*8 + (lane&3)*2;
      int n  = n0 + c0;
      float bv0 = g_bias_r[n], bv1 = g_bias_r[n+1];
      float2 lo = __half22float2(*(__half2*)&acc[mi][nj][0]);  // row r0
      float2 hi = __half22float2(*(__half2*)&acc[mi][nj][1]);  // row r0+8
      __nv_bfloat162 v0, v1;
      v0.x = __float2bfloat16(lo.x*INV_SC2 + bv0);
      v0.y = __float2bfloat16(lo.y*INV_SC2 + bv1);
      v1.x = __float2bfloat16(hi.x*INV_SC2 + bv0);
      v1.y = __float2bfloat16(hi.y*INV_SC2 + bv1);
      *(__nv_bfloat162*)&g_X[(size_t)(m0+r0)*N4H + n]   = v0;
      *(__nv_bfloat162*)&g_X[(size_t)(m0+r0+8)*N4H + n] = v1;
    }
}

// ================= persistent LSTM over 128 steps (fp8, f16 acc) =================
__global__ __launch_bounds__(512,1) void k_lstm(){
  extern __shared__ __align__(16) char sb[];

  int tid  = threadIdx.x;
  int bid  = blockIdx.x;          // 0..127
  int grp  = bid >> 5;            // batch-tile group 0..3
  int b0 = grp * 128;
  int n0 = (bid & 31) * 128;
  unsigned* bar = &g_bar4[grp*32];

  int lane = tid & 31, warp = tid >> 5;
  int wm = warp >> 2, wn = warp & 3;
  bool evenl = ((lane & 1) == 0);
  uint32_t smembase = su32(sb);

  uint32_t aoff = (uint32_t)((wm*32 + (lane & 15))*ROWB + ((lane >> 4) << 4));
  uint32_t boff = (uint32_t)(ATILE + (wn*32 + (lane & 7) + (((lane >> 4) & 1) << 3))*ROWB
                             + (((lane >> 3) & 1) << 4));

  float cst[8], hmx[8];
  #pragma unroll
  for (int i=0;i<8;i++){ cst[i]=0.f; hmx[i]=-3.4e38f; }

  const int NC = HID / KC;  // 8

  #pragma unroll 1
  for (int t = 0; t < TT; t++){
    uint32_t acc[2][4][2];
    #pragma unroll
    for (int a=0;a<2;a++)
      #pragma unroll
      for (int b=0;b<4;b++){ acc[a][b][0]=0u; acc[a][b][1]=0u; }

    if (t > 0){
      const unsigned char* Hp = g_Hbuf[(t-1)&1];

      auto fill = [&](int kc){
        int s = kc % NSTG;
        uint32_t base = smembase + s*STAGEB;
        int k0 = kc * KC;
        #pragma unroll
        for (int p=0; p<2; p++){
          int seg = tid + p*512;
          int row = seg >> 3, cs = seg & 7;
          uint32_t d = base + row*ROWB + cs*16;
          cp16(d,         Hp + (size_t)(b0+row)*HID + k0 + cs*16);
          cp16(d + ATILE, g_Whh_f8 + (size_t)(n0+row)*HID + k0 + cs*16);
        }
        cp_commit();
      };

      fill(0); fill(1);

      #pragma unroll 1
      for (int kc = 0; kc < NC; kc++){
        if (kc < NC-1) cp_wait1(); else cp_wait0();
        __syncthreads();
        if (kc + 2 < NC) fill(kc + 2);

        uint32_t ab = smembase + (kc % NSTG)*STAGEB + aoff;
        uint32_t bb = smembase + (kc % NSTG)*STAGEB + boff;
        #pragma unroll
        for (int kk = 0; kk < 4; kk++){
          uint32_t ko = kk*32;
          uint32_t afr[2][4], bfr[2][4];
          ldm_x4(afr[0], ab + ko);
          ldm_x4(afr[1], ab + 16*ROWB + ko);
          ldm_x4(bfr[0], bb + ko);
          ldm_x4(bfr[1], bb + 16*ROWB + ko);
          #pragma unroll
          for (int mi=0; mi<2; mi++){
            mma_f8h(acc[mi][0], afr[mi], &bfr[0][0]);
            mma_f8h(acc[mi][1], afr[mi], &bfr[0][2]);
            mma_f8h(acc[mi][2], afr[mi], &bfr[1][0]);
            mma_f8h(acc[mi][3], afr[mi], &bfr[1][2]);
          }
        }
      }
    }

    // fused LSTM pointwise; cols are 4h+gate so a lane pair owns all 4 gates of one h
    unsigned char* Hc = g_Hbuf[t&1];
    #pragma unroll
    for (int mi=0; mi<2; mi++)
      #pragma unroll
      for (int nj=0; nj<4; nj++){
        int r0 = wm*32 + mi*16 + (lane>>2);
        int c0 = wn*32 + nj*8 + (lane&3)*2;
        size_t mbase = ((size_t)t*BQ + b0 + r0)*N4H + n0 + c0;
        float2 x0 = __bfloat1622float2(*(const __nv_bfloat162*)&g_X[mbase]);
        float2 x1 = __bfloat1622float2(*(const __nv_bfloat162*)&g_X[mbase + (size_t)8*N4H]);
        float2 lo = __half22float2(*(__half2*)&acc[mi][nj][0]);
        float2 hi = __half22float2(*(__half2*)&acc[mi][nj][1]);
        float d0 = lo.x*INV_SC2 + x0.x;
        float d1 = lo.y*INV_SC2 + x0.y;
        float d2 = hi.x*INV_SC2 + x1.x;
        float d3 = hi.y*INV_SC2 + x1.y;
        float s0 = evenl ? d2 : d0;
        float s1 = evenl ? d3 : d1;
        float e0 = __shfl_xor_sync(0xffffffffu, s0, 1);
        float e1 = __shfl_xor_sync(0xffffffffu, s1, 1);
        float gi = evenl ? d0 : e0;
        float gf = evenl ? d1 : e1;
        float gg = evenl ? e0 : d2;
        float go = evenl ? e1 : d3;
        float ii = sigf(gi), ff = sigf(gf), g = tanhf_(gg), oo = sigf(go);
        int si = mi*4 + nj;
        float cc = ff*cst[si] + ii*g;
        cst[si] = cc;
        float hn = oo * tanhf_(cc);
        hmx[si] = fmaxf(hmx[si], hn);
        int rr = r0 + (evenl ? 0 : 8);
        int hg = (bid & 31)*32 + wn*8 + nj*2 + ((lane&3)>>1);
        Hc[(size_t)(b0+rr)*HID + hg] = to_f8(hn*SCALE_IN);
      }

    // per-group barrier (32 co-resident CTAs per batch tile, reset by k_prep)
    __syncthreads();
    if (tid == 0){
      __threadfence();
      atomicAdd(bar, 1u);
      unsigned target = (unsigned)(t+1) * 32u;
      unsigned v;
      do {
        asm volatile("ld.acquire.gpu.global.u32 %0, [%1];" : "=r"(v) : "l"(bar) : "memory");
      } while (v < target);
    }
    __syncthreads();
  }

  // write max-pooled h
  #pragma unroll
  for (int mi=0; mi<2; mi++)
    #pragma unroll
    for (int nj=0; nj<4; nj++){
      int r0 = wm*32 + mi*16 + (lane>>2);
      int rr = r0 + (evenl ? 0 : 8);
      int hg = (bid & 31)*32 + wn*8 + nj*2 + ((lane&3)>>1);
      g_Hmax[(size_t)(b0+rr)*HID + hg] = hmx[mi*4+nj];
    }
}

// ---------------- final linear + sigmoid ----------------
__global__ void k_final(const float* __restrict__ Wl, const float* __restrict__ bl,
                        float* __restrict__ out){
  int b = blockIdx.x;
  int tid = threadIdx.x;        // 128
  float s0 = 0.f, s1 = 0.f;
  for (int h = tid; h < HID; h += 128){
    float hq = g_Hmax[(size_t)b*HID + h];
    float hs = g_Hmax[(size_t)(b+NB)*HID + h];
    s0 += hq*Wl[h]         + hs*Wl[HID + h];
    s1 += hq*Wl[2*HID + h] + hs*Wl[3*HID + h];
  }
  #pragma unroll
  for (int o = 16; o; o >>= 1){
    s0 += __shfl_xor_sync(0xffffffffu, s0, o);
    s1 += __shfl_xor_sync(0xffffffffu, s1, o);
  }
  __shared__ float r0[4], r1[4];
  if ((tid & 31) == 0){ r0[tid>>5] = s0; r1[tid>>5] = s1; }
  __syncthreads();
  if (tid == 0){
    float t0 = r0[0]+r0[1]+r0[2]+r0[3] + bl[0];
    float t1 = r1[0]+r1[1]+r1[2]+r1[3] + bl[1];
    out[b*2+0] = 1.f/(1.f+__expf(-t0));
    out[b*2+1] = 1.f/(1.f+__expf(-t1));
  }
}

// ---------------- launcher ----------------
extern "C" void kernel_launch(void* const* d_in, const int* in_sizes, int n_in,
                              void* d_out, int out_size){
  const int*   question = (const int*)  d_in[0];
  const int*   sentence = (const int*)  d_in[1];
  const float* emb      = (const float*)d_in[2];
  const float* W_ih     = (const float*)d_in[3];
  const float* W_hh     = (const float*)d_in[4];
  const float* b_ih     = (const float*)d_in[5];
  const float* b_hh     = (const float*)d_in[6];
  const float* W_last   = (const float*)d_in[7];
  const float* b_last   = (const float*)d_in[8];
  float* out = (float*)d_out;

  static bool attr_done = false;
  if (!attr_done){
    cudaFuncSetAttribute(k_xgemm, cudaFuncAttributeMaxDynamicSharedMemorySize, SMEMB);
    cudaFuncSetAttribute(k_lstm,  cudaFuncAttributeMaxDynamicSharedMemorySize, SMEMB);
    attr_done = true;
  }

  k_cast_emb<<<2048, 256>>>(emb);
  k_prep<<<1024, 256>>>(W_ih, W_hh, b_ih, b_hh);

  dim3 gx(32, 512);
  k_xgemm<<<gx, 512, SMEMB>>>(question, sentence);

  k_lstm<<<128, 512, SMEMB>>>();

  k_final<<<256, 128>>>(W_last, b_last, out);
}

// round 15
// speedup vs baseline: 1.4380x; 1.4380x over previous
#include <cuda_runtime.h>
#include <cuda_bf16.h>
#include <cuda_fp16.h>
#include <cuda_fp8.h>
#include <cstdint>
#include <cstddef>

#define VOCAB 91557
#define WD    512
#define HID   1024
#define NB    256
#define TT    128
#define BQ    512
#define N4H   4096
#define MX    (BQ*TT)

#define KC     128                // K chunk in fp8 elems (=128 B)
#define ROWB   144                // padded row bytes
#define ATILE  (128*ROWB)         // 18432 B per operand chunk
#define STAGEB (2*ATILE)          // A+B = 36864 B
#define NSTG   3
#define SMEMB  (NSTG*STAGEB)      // 110592 B

#define SCALE_IN   64.0f
#define INV_SC2    (1.0f/4096.0f)

// ---------------- static scratch (no allocs allowed) ----------------
__device__ unsigned char g_emb_f8[(size_t)VOCAB*WD];        // ~47 MB
__device__ unsigned char g_Wih_f8[(size_t)N4H*WD];          // 2 MB, col = 4*h+gate
__device__ unsigned char g_Whh_f8[(size_t)N4H*HID];         // 4 MB
__device__ float         g_bias_r[N4H];
__device__ __nv_bfloat16 g_X[(size_t)MX*N4H];               // 512 MB bf16
__device__ unsigned char g_Hbuf[2][(size_t)BQ*HID];         // fp8, x64 scaled
__device__ float         g_Hmax[(size_t)BQ*HID];
__device__ unsigned      g_bar4[4*32];                      // 4 group counters, 128B apart

__device__ __forceinline__ float sigf(float x){ return 1.f/(1.f+__expf(-x)); }
__device__ __forceinline__ float tanhf_(float x){ return 2.f/(1.f+__expf(-2.f*x)) - 1.f; }

__device__ __forceinline__ unsigned char to_f8(float x){
  return (unsigned char)__nv_cvt_float_to_fp8(x, __NV_SATFINITE, __NV_E4M3);
}

// fp8 e4m3 mma, m16n8k32, fp16 accumulate (2 packed regs)
__device__ __forceinline__ void mma_f8h(uint32_t* c, const uint32_t* a, const uint32_t* b){
  asm volatile(
    "mma.sync.aligned.m16n8k32.row.col.f16.e4m3.e4m3.f16 "
    "{%0,%1}, {%2,%3,%4,%5}, {%6,%7}, {%0,%1};\n"
    : "+r"(c[0]), "+r"(c[1])
    : "r"(a[0]), "r"(a[1]), "r"(a[2]), "r"(a[3]), "r"(b[0]), "r"(b[1]));
}

__device__ __forceinline__ void ldm_x4(uint32_t* r, uint32_t addr){
  asm volatile("ldmatrix.sync.aligned.m8n8.x4.shared.b16 {%0,%1,%2,%3}, [%4];"
    : "=r"(r[0]), "=r"(r[1]), "=r"(r[2]), "=r"(r[3]) : "r"(addr));
}

__device__ __forceinline__ uint32_t su32(const void* p){
  uint32_t a;
  asm("{ .reg .u64 t; cvta.to.shared.u64 t, %1; cvt.u32.u64 %0, t; }" : "=r"(a) : "l"(p));
  return a;
}
__device__ __forceinline__ void cp16(uint32_t dst, const void* src){
  asm volatile("cp.async.cg.shared.global [%0], [%1], 16;\n" :: "r"(dst), "l"(src));
}
__device__ __forceinline__ void cp_commit(){ asm volatile("cp.async.commit_group;\n"); }
__device__ __forceinline__ void cp_wait0(){ asm volatile("cp.async.wait_group 0;\n"); }
__device__ __forceinline__ void cp_wait1(){ asm volatile("cp.async.wait_group 1;\n"); }
__device__ __forceinline__ void cp_wait2(){ asm volatile("cp.async.wait_group 2;\n"); }

// ---------------- prep kernels ----------------
__global__ void k_cast_emb(const float* __restrict__ emb){
  size_t n = (size_t)VOCAB*WD/4;
  size_t stride = (size_t)gridDim.x*blockDim.x;
  for (size_t i = (size_t)blockIdx.x*blockDim.x + threadIdx.x; i < n; i += stride){
    float4 v = ((const float4*)emb)[i];
    uchar4 o;
    o.x = to_f8(v.x*SCALE_IN); o.y = to_f8(v.y*SCALE_IN);
    o.z = to_f8(v.z*SCALE_IN); o.w = to_f8(v.w*SCALE_IN);
    ((uchar4*)g_emb_f8)[i] = o;
  }
}
// merged: Wih reorder + Whh reorder + bias + barrier reset
__global__ void k_prep(const float* __restrict__ Wih, const float* __restrict__ Whh,
                       const float* __restrict__ b_ih, const float* __restrict__ b_hh){
  size_t stride = (size_t)gridDim.x*blockDim.x;
  size_t i0 = (size_t)blockIdx.x*blockDim.x + threadIdx.x;
  const size_t nih = (size_t)N4H*WD;
  for (size_t i = i0; i < nih; i += stride){
    size_t nn = i / WD, k = i - nn*WD;
    size_t h = nn >> 2, g = nn & 3;
    g_Wih_f8[i] = to_f8(Wih[(g*HID + h)*WD + k]*SCALE_IN);
  }
  const size_t nhh = (size_t)N4H*HID;
  for (size_t i = i0; i < nhh; i += stride){
    size_t nn = i / HID, k = i - nn*HID;
    size_t h = nn >> 2, g = nn & 3;
    g_Whh_f8[i] = to_f8(Whh[(g*HID + h)*HID + k]*SCALE_IN);
  }
  for (size_t i = i0; i < N4H; i += stride){
    size_t h = i >> 2, g = i & 3;
    g_bias_r[i] = b_ih[g*HID + h] + b_hh[g*HID + h];
  }
  if (i0 < 4) g_bar4[i0*32] = 0u;
}

// ================= X = gather(emb) @ Wih^T + bias (fp8, f16 acc) =================
__global__ __launch_bounds__(512,1) void k_xgemm(const int* __restrict__ question,
                                                 const int* __restrict__ sentence){
  extern __shared__ __align__(16) char sb[];
  __shared__ int toks[128];

  int tid  = threadIdx.x;
  int n0   = blockIdx.x * 128;
  int m0   = blockIdx.y * 128;
  int t    = m0 / BQ;

  if (tid < 128){
    int b = (m0 % BQ) + tid;
    toks[tid] = (b < NB) ? question[b*TT + t] : sentence[(b-NB)*TT + t];
  }
  __syncthreads();

  int lane = tid & 31, warp = tid >> 5;
  int wm = warp >> 2, wn = warp & 3;          // 4x4 warp grid, 32x32 warp tiles
  uint32_t smembase = su32(sb);

  uint32_t aoff = (uint32_t)((wm*32 + (lane & 15))*ROWB + ((lane >> 4) << 4));
  uint32_t boff = (uint32_t)(ATILE + (wn*32 + (lane & 7) + (((lane >> 4) & 1) << 3))*ROWB
                             + (((lane >> 3) & 1) << 4));

  uint32_t acc[2][4][2];
  #pragma unroll
  for (int a=0;a<2;a++)
    #pragma unroll
    for (int b=0;b<4;b++){ acc[a][b][0]=0u; acc[a][b][1]=0u; }

  const int NC = WD / KC;   // 4

  auto fill = [&](int kc){
    int s = kc % NSTG;
    uint32_t base = smembase + s*STAGEB;
    int k0 = kc * KC;
    #pragma unroll
    for (int p=0; p<2; p++){
      int seg = tid + p*512;
      int row = seg >> 3, cs = seg & 7;
      uint32_t d = base + row*ROWB + cs*16;
      cp16(d,         g_emb_f8 + (size_t)toks[row]*WD + k0 + cs*16);
      cp16(d + ATILE, g_Wih_f8 + (size_t)(n0+row)*WD + k0 + cs*16);
    }
    cp_commit();
  };

  fill(0); fill(1);

  #pragma unroll 1
  for (int kc = 0; kc < NC; kc++){
    if (kc + 2 < NC) fill(kc + 2);
    if (kc < NC-2) cp_wait2(); else if (kc == NC-2) cp_wait1(); else cp_wait0();
    __syncthreads();

    uint32_t ab = smembase + (kc % NSTG)*STAGEB + aoff;
    uint32_t bb = smembase + (kc % NSTG)*STAGEB + boff;
    #pragma unroll
    for (int kk = 0; kk < 4; kk++){     // 4 sub-k of 32 fp8 (32 B)
      uint32_t ko = kk*32;
      uint32_t afr[2][4], bfr[2][4];
      ldm_x4(afr[0], ab + ko);
      ldm_x4(afr[1], ab + 16*ROWB + ko);
      ldm_x4(bfr[0], bb + ko);
      ldm_x4(bfr[1], bb + 16*ROWB + ko);
      #pragma unroll
      for (int mi=0; mi<2; mi++){
        mma_f8h(acc[mi][0], afr[mi], &bfr[0][0]);
        mma_f8h(acc[mi][1], afr[mi], &bfr[0][2]);
        mma_f8h(acc[mi][2], afr[mi], &bfr[1][0]);
        mma_f8h(acc[mi][3], afr[mi], &bfr[1][2]);
      }
    }
    __syncthreads();
  }

  // epilogue: unpack f16 acc, descale, + bias, store bf16
  #pragma unroll
  for (int mi=0; mi<2; mi++)
    #pragma unroll
    for (int nj=0; nj<4; nj++){
      int r0 = wm*32 + mi*16 + (lane>>2);
      int c0 = wn*32 + nj*8 + (lane&3)*2;
      int n  = n0 + c0;
      float bv0 = g_bias_r[n], bv1 = g_bias_r[n+1];
      float2 lo = __half22float2(*(__half2*)&acc[mi][nj][0]);  // row r0
      float2 hi = __half22float2(*(__half2*)&acc[mi][nj][1]);  // row r0+8
      __nv_bfloat162 v0, v1;
      v0.x = __float2bfloat16(lo.x*INV_SC2 + bv0);
      v0.y = __float2bfloat16(lo.y*INV_SC2 + bv1);
      v1.x = __float2bfloat16(hi.x*INV_SC2 + bv0);
      v1.y = __float2bfloat16(hi.y*INV_SC2 + bv1);
      *(__nv_bfloat162*)&g_X[(size_t)(m0+r0)*N4H + n]   = v0;
      *(__nv_bfloat162*)&g_X[(size_t)(m0+r0+8)*N4H + n] = v1;
    }
}

// ================= persistent LSTM over 128 steps (fp8, f16 acc) =================
__global__ __launch_bounds__(512,1) void k_lstm(){
  extern __shared__ __align__(16) char sb[];

  int tid  = threadIdx.x;
  int bid  = blockIdx.x;          // 0..127
  int grp  = bid >> 5;            // batch-tile group 0..3
  int b0 = grp * 128;
  int n0 = (bid & 31) * 128;
  unsigned* bar = &g_bar4[grp*32];

  int lane = tid & 31, warp = tid >> 5;
  int wm = warp >> 2, wn = warp & 3;
  bool evenl = ((lane & 1) == 0);
  uint32_t smembase = su32(sb);

  uint32_t aoff = (uint32_t)((wm*32 + (lane & 15))*ROWB + ((lane >> 4) << 4));
  uint32_t boff = (uint32_t)(ATILE + (wn*32 + (lane & 7) + (((lane >> 4) & 1) << 3))*ROWB
                             + (((lane >> 3) & 1) << 4));

  float cst[8], hmx[8];
  #pragma unroll
  for (int i=0;i<8;i++){ cst[i]=0.f; hmx[i]=-3.4e38f; }

  const int NC = HID / KC;  // 8

  #pragma unroll 1
  for (int t = 0; t < TT; t++){
    uint32_t acc[2][4][2];
    #pragma unroll
    for (int a=0;a<2;a++)
      #pragma unroll
      for (int b=0;b<4;b++){ acc[a][b][0]=0u; acc[a][b][1]=0u; }

    if (t > 0){
      const unsigned char* Hp = g_Hbuf[(t-1)&1];

      auto fill = [&](int kc){
        int s = kc % NSTG;
        uint32_t base = smembase + s*STAGEB;
        int k0 = kc * KC;
        #pragma unroll
        for (int p=0; p<2; p++){
          int seg = tid + p*512;
          int row = seg >> 3, cs = seg & 7;
          uint32_t d = base + row*ROWB + cs*16;
          cp16(d,         Hp + (size_t)(b0+row)*HID + k0 + cs*16);
          cp16(d + ATILE, g_Whh_f8 + (size_t)(n0+row)*HID + k0 + cs*16);
        }
        cp_commit();
      };

      fill(0); fill(1);

      #pragma unroll 1
      for (int kc = 0; kc < NC; kc++){
        if (kc + 2 < NC) fill(kc + 2);
        if (kc < NC-2) cp_wait2(); else if (kc == NC-2) cp_wait1(); else cp_wait0();
        __syncthreads();

        uint32_t ab = smembase + (kc % NSTG)*STAGEB + aoff;
        uint32_t bb = smembase + (kc % NSTG)*STAGEB + boff;
        #pragma unroll
        for (int kk = 0; kk < 4; kk++){
          uint32_t ko = kk*32;
          uint32_t afr[2][4], bfr[2][4];
          ldm_x4(afr[0], ab + ko);
          ldm_x4(afr[1], ab + 16*ROWB + ko);
          ldm_x4(bfr[0], bb + ko);
          ldm_x4(bfr[1], bb + 16*ROWB + ko);
          #pragma unroll
          for (int mi=0; mi<2; mi++){
            mma_f8h(acc[mi][0], afr[mi], &bfr[0][0]);
            mma_f8h(acc[mi][1], afr[mi], &bfr[0][2]);
            mma_f8h(acc[mi][2], afr[mi], &bfr[1][0]);
            mma_f8h(acc[mi][3], afr[mi], &bfr[1][2]);
          }
        }
        __syncthreads();
      }
    }

    // fused LSTM pointwise; cols are 4h+gate so a lane pair owns all 4 gates of one h
    unsigned char* Hc = g_Hbuf[t&1];
    #pragma unroll
    for (int mi=0; mi<2; mi++)
      #pragma unroll
      for (int nj=0; nj<4; nj++){
        int r0 = wm*32 + mi*16 + (lane>>2);
        int c0 = wn*32 + nj*8 + (lane&3)*2;
        size_t mbase = ((size_t)t*BQ + b0 + r0)*N4H + n0 + c0;
        float2 x0 = __bfloat1622float2(*(const __nv_bfloat162*)&g_X[mbase]);
        float2 x1 = __bfloat1622float2(*(const __nv_bfloat162*)&g_X[mbase + (size_t)8*N4H]);
        float2 lo = __half22float2(*(__half2*)&acc[mi][nj][0]);
        float2 hi = __half22float2(*(__half2*)&acc[mi][nj][1]);
        float d0 = lo.x*INV_SC2 + x0.x;
        float d1 = lo.y*INV_SC2 + x0.y;
        float d2 = hi.x*INV_SC2 + x1.x;
        float d3 = hi.y*INV_SC2 + x1.y;
        float s0 = evenl ? d2 : d0;
        float s1 = evenl ? d3 : d1;
        float e0 = __shfl_xor_sync(0xffffffffu, s0, 1);
        float e1 = __shfl_xor_sync(0xffffffffu, s1, 1);
        float gi = evenl ? d0 : e0;
        float gf = evenl ? d1 : e1;
        float gg = evenl ? e0 : d2;
        float go = evenl ? e1 : d3;
        float ii = sigf(gi), ff = sigf(gf), g = tanhf_(gg), oo = sigf(go);
        int si = mi*4 + nj;
        float cc = ff*cst[si] + ii*g;
        cst[si] = cc;
        float hn = oo * tanhf_(cc);
        hmx[si] = fmaxf(hmx[si], hn);
        int rr = r0 + (evenl ? 0 : 8);
        int hg = (bid & 31)*32 + wn*8 + nj*2 + ((lane&3)>>1);
        Hc[(size_t)(b0+rr)*HID + hg] = to_f8(hn*SCALE_IN);
      }

    // per-group barrier (32 CTAs per batch tile, reset by k_prep)
    __syncthreads();
    if (tid == 0){
      __threadfence();
      atomicAdd(bar, 1u);
      unsigned target = (unsigned)(t+1) * 32u;
      unsigned v;
      do {
        asm volatile("ld.acquire.gpu.global.u32 %0, [%1];" : "=r"(v) : "l"(bar) : "memory");
      } while (v < target);
    }
    __syncthreads();
  }

  // write max-pooled h
  #pragma unroll
  for (int mi=0; mi<2; mi++)
    #pragma unroll
    for (int nj=0; nj<4; nj++){
      int r0 = wm*32 + mi*16 + (lane>>2);
      int rr = r0 + (evenl ? 0 : 8);
      int hg = (bid & 31)*32 + wn*8 + nj*2 + ((lane&3)>>1);
      g_Hmax[(size_t)(b0+rr)*HID + hg] = hmx[mi*4+nj];
    }
}

// ---------------- final linear + sigmoid ----------------
__global__ void k_final(const float* __restrict__ Wl, const float* __restrict__ bl,
                        float* __restrict__ out){
  int b = blockIdx.x;
  int tid = threadIdx.x;        // 128
  float s0 = 0.f, s1 = 0.f;
  for (int h = tid; h < HID; h += 128){
    float hq = g_Hmax[(size_t)b*HID + h];
    float hs = g_Hmax[(size_t)(b+NB)*HID + h];
    s0 += hq*Wl[h]         + hs*Wl[HID + h];
    s1 += hq*Wl[2*HID + h] + hs*Wl[3*HID + h];
  }
  #pragma unroll
  for (int o = 16; o; o >>= 1){
    s0 += __shfl_xor_sync(0xffffffffu, s0, o);
    s1 += __shfl_xor_sync(0xffffffffu, s1, o);
  }
  __shared__ float r0[4], r1[4];
  if ((tid & 31) == 0){ r0[tid>>5] = s0; r1[tid>>5] = s1; }
  __syncthreads();
  if (tid == 0){
    float t0 = r0[0]+r0[1]+r0[2]+r0[3] + bl[0];
    float t1 = r1[0]+r1[1]+r1[2]+r1[3] + bl[1];
    out[b*2+0] = 1.f/(1.f+__expf(-t0));
    out[b*2+1] = 1.f/(1.f+__expf(-t1));
  }
}

// ---------------- launcher ----------------
extern "C" void kernel_launch(void* const* d_in, const int* in_sizes, int n_in,
                              void* d_out, int out_size){
  const int*   question = (const int*)  d_in[0];
  const int*   sentence = (const int*)  d_in[1];
  const float* emb      = (const float*)d_in[2];
  const float* W_ih     = (const float*)d_in[3];
  const float* W_hh     = (const float*)d_in[4];
  const float* b_ih     = (const float*)d_in[5];
  const float* b_hh     = (const float*)d_in[6];
  const float* W_last   = (const float*)d_in[7];
  const float* b_last   = (const float*)d_in[8];
  float* out = (float*)d_out;

  static bool attr_done = false;
  if (!attr_done){
    cudaFuncSetAttribute(k_xgemm, cudaFuncAttributeMaxDynamicSharedMemorySize, SMEMB);
    cudaFuncSetAttribute(k_lstm,  cudaFuncAttributeMaxDynamicSharedMemorySize, SMEMB);
    attr_done = true;
  }

  k_cast_emb<<<2048, 256>>>(emb);
  k_prep<<<1024, 256>>>(W_ih, W_hh, b_ih, b_hh);

  dim3 gx(32, 512);
  k_xgemm<<<gx, 512, SMEMB>>>(question, sentence);

  k_lstm<<<128, 512, SMEMB>>>();

  k_final<<<256, 128>>>(W_last, b_last, out);
}

// round 16
// speedup vs baseline: 1.5434x; 1.0733x over previous
#include <cuda_runtime.h>
#include <cuda_bf16.h>
#include <cuda_fp16.h>
#include <cuda_fp8.h>
#include <cstdint>
#include <cstddef>

#define VOCAB 91557
#define WD    512
#define HID   1024
#define NB    256
#define TT    128
#define BQ    512
#define N4H   4096
#define MX    (BQ*TT)

#define KC     128                // K chunk in fp8 elems (=128 B)
#define ROWB   144                // padded row bytes
#define ATILE  (128*ROWB)         // A chunk: 128 rows = 18432 B
#define BTILE  (64*ROWB)          // B chunk: 64 rows  = 9216 B
#define STAGEB (ATILE+BTILE)      // 27648 B
#define NSTG   3
#define SMEMB  (NSTG*STAGEB)      // 82944 B  -> 2 CTAs/SM

#define SCALE_IN   64.0f
#define INV_SC2    (1.0f/4096.0f)

// ---------------- static scratch (no allocs allowed) ----------------
__device__ unsigned char g_emb_f8[(size_t)VOCAB*WD];        // ~47 MB
__device__ unsigned char g_Wih_f8[(size_t)N4H*WD];          // 2 MB, col = 4*h+gate
__device__ unsigned char g_Whh_f8[(size_t)N4H*HID];         // 4 MB
__device__ float         g_bias_r[N4H];
__device__ __nv_bfloat16 g_X[(size_t)MX*N4H];               // 512 MB bf16
__device__ unsigned char g_Hbuf[2][(size_t)BQ*HID];         // fp8, x64 scaled
__device__ float         g_Hmax[(size_t)BQ*HID];
__device__ unsigned      g_bar4[4*32];                      // 4 group counters, 128B apart

__device__ __forceinline__ float sigf(float x){ return 1.f/(1.f+__expf(-x)); }
__device__ __forceinline__ float tanhf_(float x){ return 2.f/(1.f+__expf(-2.f*x)) - 1.f; }

__device__ __forceinline__ unsigned char to_f8(float x){
  return (unsigned char)__nv_cvt_float_to_fp8(x, __NV_SATFINITE, __NV_E4M3);
}

// fp8 e4m3 mma, m16n8k32, fp16 accumulate (2 packed regs)
__device__ __forceinline__ void mma_f8h(uint32_t* c, const uint32_t* a, const uint32_t* b){
  asm volatile(
    "mma.sync.aligned.m16n8k32.row.col.f16.e4m3.e4m3.f16 "
    "{%0,%1}, {%2,%3,%4,%5}, {%6,%7}, {%0,%1};\n"
    : "+r"(c[0]), "+r"(c[1])
    : "r"(a[0]), "r"(a[1]), "r"(a[2]), "r"(a[3]), "r"(b[0]), "r"(b[1]));
}

__device__ __forceinline__ void ldm_x4(uint32_t* r, uint32_t addr){
  asm volatile("ldmatrix.sync.aligned.m8n8.x4.shared.b16 {%0,%1,%2,%3}, [%4];"
    : "=r"(r[0]), "=r"(r[1]), "=r"(r[2]), "=r"(r[3]) : "r"(addr));
}

__device__ __forceinline__ uint32_t su32(const void* p){
  uint32_t a;
  asm("{ .reg .u64 t; cvta.to.shared.u64 t, %1; cvt.u32.u64 %0, t; }" : "=r"(a) : "l"(p));
  return a;
}
__device__ __forceinline__ void cp16(uint32_t dst, const void* src){
  asm volatile("cp.async.cg.shared.global [%0], [%1], 16;\n" :: "r"(dst), "l"(src));
}
__device__ __forceinline__ void cp_commit(){ asm volatile("cp.async.commit_group;\n"); }
__device__ __forceinline__ void cp_wait0(){ asm volatile("cp.async.wait_group 0;\n"); }
__device__ __forceinline__ void cp_wait1(){ asm volatile("cp.async.wait_group 1;\n"); }
__device__ __forceinline__ void cp_wait2(){ asm volatile("cp.async.wait_group 2;\n"); }

// ---------------- prep kernels ----------------
__global__ void k_cast_emb(const float* __restrict__ emb){
  size_t n = (size_t)VOCAB*WD/4;
  size_t stride = (size_t)gridDim.x*blockDim.x;
  for (size_t i = (size_t)blockIdx.x*blockDim.x + threadIdx.x; i < n; i += stride){
    float4 v = ((const float4*)emb)[i];
    uchar4 o;
    o.x = to_f8(v.x*SCALE_IN); o.y = to_f8(v.y*SCALE_IN);
    o.z = to_f8(v.z*SCALE_IN); o.w = to_f8(v.w*SCALE_IN);
    ((uchar4*)g_emb_f8)[i] = o;
  }
}
// merged: Wih reorder + Whh reorder + bias + barrier reset
__global__ void k_prep(const float* __restrict__ Wih, const float* __restrict__ Whh,
                       const float* __restrict__ b_ih, const float* __restrict__ b_hh){
  size_t stride = (size_t)gridDim.x*blockDim.x;
  size_t i0 = (size_t)blockIdx.x*blockDim.x + threadIdx.x;
  const size_t nih = (size_t)N4H*WD;
  for (size_t i = i0; i < nih; i += stride){
    size_t nn = i / WD, k = i - nn*WD;
    size_t h = nn >> 2, g = nn & 3;
    g_Wih_f8[i] = to_f8(Wih[(g*HID + h)*WD + k]*SCALE_IN);
  }
  const size_t nhh = (size_t)N4H*HID;
  for (size_t i = i0; i < nhh; i += stride){
    size_t nn = i / HID, k = i - nn*HID;
    size_t h = nn >> 2, g = nn & 3;
    g_Whh_f8[i] = to_f8(Whh[(g*HID + h)*HID + k]*SCALE_IN);
  }
  for (size_t i = i0; i < N4H; i += stride){
    size_t h = i >> 2, g = i & 3;
    g_bias_r[i] = b_ih[g*HID + h] + b_hh[g*HID + h];
  }
  if (i0 < 4) g_bar4[i0*32] = 0u;
}

// ================= X = gather(emb) @ Wih^T + bias =================
// 256 threads, CTA tile 128Mx64N, 4 K-chunks, 3-stage ring, 2 CTAs/SM
__global__ __launch_bounds__(256,2) void k_xgemm(const int* __restrict__ question,
                                                 const int* __restrict__ sentence){
  extern __shared__ __align__(16) char sb[];
  __shared__ int toks[128];
  __shared__ float sbias[64];

  int tid  = threadIdx.x;
  int n0   = blockIdx.x * 64;    // over 4096, 64 tiles
  int m0   = blockIdx.y * 128;   // over 65536, 512 tiles
  int t    = m0 / BQ;

  if (tid < 128){
    int b = (m0 % BQ) + tid;
    toks[tid] = (b < NB) ? question[b*TT + t] : sentence[(b-NB)*TT + t];
  }
  if (tid < 64) sbias[tid] = g_bias_r[n0 + tid];
  __syncthreads();

  int lane = tid & 31, warp = tid >> 5;   // 8 warps
  int wm = warp >> 1, wn = warp & 1;      // 4x2 grid, warp tile 32x32
  uint32_t smembase = su32(sb);

  uint32_t aoff = (uint32_t)((wm*32 + (lane & 15))*ROWB + ((lane >> 4) << 4));
  uint32_t boff = (uint32_t)(ATILE + (wn*32 + (lane & 7) + (((lane >> 4) & 1) << 3))*ROWB
                             + (((lane >> 3) & 1) << 4));

  uint32_t acc[2][4][2];
  #pragma unroll
  for (int a=0;a<2;a++)
    #pragma unroll
    for (int b=0;b<4;b++){ acc[a][b][0]=0u; acc[a][b][1]=0u; }

  const int NC = WD / KC;   // 4

  auto fill = [&](int kc){
    int s = kc % NSTG;
    uint32_t base = smembase + s*STAGEB;
    int k0 = kc * KC;
    #pragma unroll
    for (int p=0; p<4; p++){             // A: 128 rows x 8 segs = 1024
      int seg = tid + p*256;
      int row = seg >> 3, cs = seg & 7;
      cp16(base + row*ROWB + cs*16, g_emb_f8 + (size_t)toks[row]*WD + k0 + cs*16);
    }
    #pragma unroll
    for (int p=0; p<2; p++){             // B: 64 rows x 8 segs = 512
      int seg = tid + p*256;
      int row = seg >> 3, cs = seg & 7;
      cp16(base + ATILE + row*ROWB + cs*16, g_Wih_f8 + (size_t)(n0+row)*WD + k0 + cs*16);
    }
    cp_commit();
  };

  fill(0); fill(1);

  #pragma unroll 1
  for (int kc = 0; kc < NC; kc++){
    if (kc + 2 < NC) fill(kc + 2);
    if (kc < NC-2) cp_wait2(); else if (kc == NC-2) cp_wait1(); else cp_wait0();
    __syncthreads();

    uint32_t ab = smembase + (kc % NSTG)*STAGEB + aoff;
    uint32_t bb = smembase + (kc % NSTG)*STAGEB + boff;
    #pragma unroll
    for (int kk = 0; kk < 4; kk++){     // 4 sub-k of 32 fp8 (32 B)
      uint32_t ko = kk*32;
      uint32_t afr[2][4], bfr[2][4];
      ldm_x4(afr[0], ab + ko);
      ldm_x4(afr[1], ab + 16*ROWB + ko);
      ldm_x4(bfr[0], bb + ko);
      ldm_x4(bfr[1], bb + 16*ROWB + ko);
      #pragma unroll
      for (int mi=0; mi<2; mi++){
        mma_f8h(acc[mi][0], afr[mi], &bfr[0][0]);
        mma_f8h(acc[mi][1], afr[mi], &bfr[0][2]);
        mma_f8h(acc[mi][2], afr[mi], &bfr[1][0]);
        mma_f8h(acc[mi][3], afr[mi], &bfr[1][2]);
      }
    }
    __syncthreads();
  }

  // epilogue: unpack f16 acc, descale, + bias, store bf16
  #pragma unroll
  for (int mi=0; mi<2; mi++)
    #pragma unroll
    for (int nj=0; nj<4; nj++){
      int r0 = wm*32 + mi*16 + (lane>>2);
      int c0 = wn*32 + nj*8 + (lane&3)*2;
      int n  = n0 + c0;
      float bv0 = sbias[c0], bv1 = sbias[c0+1];
      float2 lo = __half22float2(*(__half2*)&acc[mi][nj][0]);  // row r0
      float2 hi = __half22float2(*(__half2*)&acc[mi][nj][1]);  // row r0+8
      __nv_bfloat162 v0, v1;
      v0.x = __float2bfloat16(lo.x*INV_SC2 + bv0);
      v0.y = __float2bfloat16(lo.y*INV_SC2 + bv1);
      v1.x = __float2bfloat16(hi.x*INV_SC2 + bv0);
      v1.y = __float2bfloat16(hi.y*INV_SC2 + bv1);
      *(__nv_bfloat162*)&g_X[(size_t)(m0+r0)*N4H + n]   = v0;
      *(__nv_bfloat162*)&g_X[(size_t)(m0+r0+8)*N4H + n] = v1;
    }
}

// ================= persistent LSTM over 128 steps =================
// 256 CTAs x 256 threads, CTA tile 128Mx64N, 8 K-chunks, 2 CTAs/SM
__global__ __launch_bounds__(256,2) void k_lstm(){
  extern __shared__ __align__(16) char sb[];

  int tid  = threadIdx.x;
  int bid  = blockIdx.x;          // 0..255
  int grp  = bid >> 6;            // batch-tile group 0..3 (64 CTAs each)
  int b0 = grp * 128;
  int ctan = bid & 63;
  int n0 = ctan * 64;
  unsigned* bar = &g_bar4[grp*32];

  int lane = tid & 31, warp = tid >> 5;   // 8 warps
  int wm = warp >> 1, wn = warp & 1;      // 4x2 grid, warp tile 32x32
  bool evenl = ((lane & 1) == 0);
  uint32_t smembase = su32(sb);

  uint32_t aoff = (uint32_t)((wm*32 + (lane & 15))*ROWB + ((lane >> 4) << 4));
  uint32_t boff = (uint32_t)(ATILE + (wn*32 + (lane & 7) + (((lane >> 4) & 1) << 3))*ROWB
                             + (((lane >> 3) & 1) << 4));

  float cst[8], hmx[8];
  #pragma unroll
  for (int i=0;i<8;i++){ cst[i]=0.f; hmx[i]=-3.4e38f; }

  const int NC = HID / KC;  // 8

  #pragma unroll 1
  for (int t = 0; t < TT; t++){
    uint32_t acc[2][4][2];
    #pragma unroll
    for (int a=0;a<2;a++)
      #pragma unroll
      for (int b=0;b<4;b++){ acc[a][b][0]=0u; acc[a][b][1]=0u; }

    if (t > 0){
      const unsigned char* Hp = g_Hbuf[(t-1)&1];

      auto fill = [&](int kc){
        int s = kc % NSTG;
        uint32_t base = smembase + s*STAGEB;
        int k0 = kc * KC;
        #pragma unroll
        for (int p=0; p<4; p++){           // A (H): 128 rows
          int seg = tid + p*256;
          int row = seg >> 3, cs = seg & 7;
          cp16(base + row*ROWB + cs*16, Hp + (size_t)(b0+row)*HID + k0 + cs*16);
        }
        #pragma unroll
        for (int p=0; p<2; p++){           // B (Whh): 64 rows
          int seg = tid + p*256;
          int row = seg >> 3, cs = seg & 7;
          cp16(base + ATILE + row*ROWB + cs*16,
               g_Whh_f8 + (size_t)(n0+row)*HID + k0 + cs*16);
        }
        cp_commit();
      };

      fill(0); fill(1);

      #pragma unroll 1
      for (int kc = 0; kc < NC; kc++){
        if (kc + 2 < NC) fill(kc + 2);
        if (kc < NC-2) cp_wait2(); else if (kc == NC-2) cp_wait1(); else cp_wait0();
        __syncthreads();

        uint32_t ab = smembase + (kc % NSTG)*STAGEB + aoff;
        uint32_t bb = smembase + (kc % NSTG)*STAGEB + boff;
        #pragma unroll
        for (int kk = 0; kk < 4; kk++){
          uint32_t ko = kk*32;
          uint32_t afr[2][4], bfr[2][4];
          ldm_x4(afr[0], ab + ko);
          ldm_x4(afr[1], ab + 16*ROWB + ko);
          ldm_x4(bfr[0], bb + ko);
          ldm_x4(bfr[1], bb + 16*ROWB + ko);
          #pragma unroll
          for (int mi=0; mi<2; mi++){
            mma_f8h(acc[mi][0], afr[mi], &bfr[0][0]);
            mma_f8h(acc[mi][1], afr[mi], &bfr[0][2]);
            mma_f8h(acc[mi][2], afr[mi], &bfr[1][0]);
            mma_f8h(acc[mi][3], afr[mi], &bfr[1][2]);
          }
        }
        __syncthreads();
      }
    }

    // fused LSTM pointwise; cols are 4h+gate so a lane pair owns all 4 gates of one h
    unsigned char* Hc = g_Hbuf[t&1];
    #pragma unroll
    for (int mi=0; mi<2; mi++)
      #pragma unroll
      for (int nj=0; nj<4; nj++){
        int r0 = wm*32 + mi*16 + (lane>>2);
        int c0 = wn*32 + nj*8 + (lane&3)*2;
        size_t mbase = ((size_t)t*BQ + b0 + r0)*N4H + n0 + c0;
        float2 x0 = __bfloat1622float2(*(const __nv_bfloat162*)&g_X[mbase]);
        float2 x1 = __bfloat1622float2(*(const __nv_bfloat162*)&g_X[mbase + (size_t)8*N4H]);
        float2 lo = __half22float2(*(__half2*)&acc[mi][nj][0]);
        float2 hi = __half22float2(*(__half2*)&acc[mi][nj][1]);
        float d0 = lo.x*INV_SC2 + x0.x;
        float d1 = lo.y*INV_SC2 + x0.y;
        float d2 = hi.x*INV_SC2 + x1.x;
        float d3 = hi.y*INV_SC2 + x1.y;
        float s0 = evenl ? d2 : d0;
        float s1 = evenl ? d3 : d1;
        float e0 = __shfl_xor_sync(0xffffffffu, s0, 1);
        float e1 = __shfl_xor_sync(0xffffffffu, s1, 1);
        float gi = evenl ? d0 : e0;
        float gf = evenl ? d1 : e1;
        float gg = evenl ? e0 : d2;
        float go = evenl ? e1 : d3;
        float ii = sigf(gi), ff = sigf(gf), g = tanhf_(gg), oo = sigf(go);
        int si = mi*4 + nj;
        float cc = ff*cst[si] + ii*g;
        cst[si] = cc;
        float hn = oo * tanhf_(cc);
        hmx[si] = fmaxf(hmx[si], hn);
        int rr = r0 + (evenl ? 0 : 8);
        int hg = ctan*16 + wn*8 + nj*2 + ((lane&3)>>1);
        Hc[(size_t)(b0+rr)*HID + hg] = to_f8(hn*SCALE_IN);
      }

    // per-group barrier (64 co-resident CTAs per batch tile, reset by k_prep)
    __syncthreads();
    if (tid == 0){
      __threadfence();
      atomicAdd(bar, 1u);
      unsigned target = (unsigned)(t+1) * 64u;
      unsigned v;
      do {
        asm volatile("ld.acquire.gpu.global.u32 %0, [%1];" : "=r"(v) : "l"(bar) : "memory");
      } while (v < target);
    }
    __syncthreads();
  }

  // write max-pooled h
  #pragma unroll
  for (int mi=0; mi<2; mi++)
    #pragma unroll
    for (int nj=0; nj<4; nj++){
      int r0 = wm*32 + mi*16 + (lane>>2);
      int rr = r0 + (evenl ? 0 : 8);
      int hg = ctan*16 + wn*8 + nj*2 + ((lane&3)>>1);
      g_Hmax[(size_t)(b0+rr)*HID + hg] = hmx[mi*4+nj];
    }
}

// ---------------- final linear + sigmoid ----------------
__global__ void k_final(const float* __restrict__ Wl, const float* __restrict__ bl,
                        float* __restrict__ out){
  int b = blockIdx.x;
  int tid = threadIdx.x;        // 128
  float s0 = 0.f, s1 = 0.f;
  for (int h = tid; h < HID; h += 128){
    float hq = g_Hmax[(size_t)b*HID + h];
    float hs = g_Hmax[(size_t)(b+NB)*HID + h];
    s0 += hq*Wl[h]         + hs*Wl[HID + h];
    s1 += hq*Wl[2*HID + h] + hs*Wl[3*HID + h];
  }
  #pragma unroll
  for (int o = 16; o; o >>= 1){
    s0 += __shfl_xor_sync(0xffffffffu, s0, o);
    s1 += __shfl_xor_sync(0xffffffffu, s1, o);
  }
  __shared__ float r0[4], r1[4];
  if ((tid & 31) == 0){ r0[tid>>5] = s0; r1[tid>>5] = s1; }
  __syncthreads();
  if (tid == 0){
    float t0 = r0[0]+r0[1]+r0[2]+r0[3] + bl[0];
    float t1 = r1[0]+r1[1]+r1[2]+r1[3] + bl[1];
    out[b*2+0] = 1.f/(1.f+__expf(-t0));
    out[b*2+1] = 1.f/(1.f+__expf(-t1));
  }
}

// ---------------- launcher ----------------
extern "C" void kernel_launch(void* const* d_in, const int* in_sizes, int n_in,
                              void* d_out, int out_size){
  const int*   question = (const int*)  d_in[0];
  const int*   sentence = (const int*)  d_in[1];
  const float* emb      = (const float*)d_in[2];
  const float* W_ih     = (const float*)d_in[3];
  const float* W_hh     = (const float*)d_in[4];
  const float* b_ih     = (const float*)d_in[5];
  const float* b_hh     = (const float*)d_in[6];
  const float* W_last   = (const float*)d_in[7];
  const float* b_last   = (const float*)d_in[8];
  float* out = (float*)d_out;

  static bool attr_done = false;
  if (!attr_done){
    cudaFuncSetAttribute(k_xgemm, cudaFuncAttributeMaxDynamicSharedMemorySize, SMEMB);
    cudaFuncSetAttribute(k_lstm,  cudaFuncAttributeMaxDynamicSharedMemorySize, SMEMB);
    attr_done = true;
  }

  k_cast_emb<<<2048, 256>>>(emb);
  k_prep<<<1024, 256>>>(W_ih, W_hh, b_ih, b_hh);

  dim3 gx(64, 512);
  k_xgemm<<<gx, 256, SMEMB>>>(question, sentence);

  k_lstm<<<256, 256, SMEMB>>>();

  k_final<<<256, 128>>>(W_last, b_last, out);
}